// round 6
// baseline (speedup 1.0000x reference)
#include <cuda_runtime.h>
#include <cstdint>

typedef unsigned long long u64;

// ---------------- problem constants ----------------
#define BATCH 16
#define WSTRIDE 32768   // per-batch factor block: 4 * 1024 * 8

// ---------------- device scratch ----------------
__device__ float g_lnT[1024 * 16];   // LN(ada) transposed: [k][b]
__device__ float g_hT [1024 * 16];   // h transposed: [k][b]
// factors, PRE-TRANSPOSED: [b][f][r][d], f: 0=a1, 1=bb1, 2=a2, 3=bb2
__device__ float g_w  [16 * 32768];

// ---------------- f32x2 helpers ----------------
__device__ __forceinline__ u64 pk2(float lo, float hi) {
    u64 r; asm("mov.b64 %0, {%1,%2};" : "=l"(r) : "f"(lo), "f"(hi)); return r;
}
__device__ __forceinline__ void upk2(u64 v, float& lo, float& hi) {
    asm("mov.b64 {%0,%1}, %2;" : "=f"(lo), "=f"(hi) : "l"(v));
}
__device__ __forceinline__ u64 dup2(float x) { return pk2(x, x); }
__device__ __forceinline__ u64 fma2(u64 a, u64 b, u64 c) {
    u64 d; asm("fma.rn.f32x2 %0, %1, %2, %3;" : "=l"(d) : "l"(a), "l"(b), "l"(c)); return d;
}
__device__ __forceinline__ u64 mul2(u64 a, u64 b) {
    u64 d; asm("mul.rn.f32x2 %0, %1, %2;" : "=l"(d) : "l"(a), "l"(b)); return d;
}
__device__ __forceinline__ u64 add2(u64 a, u64 b) {
    u64 d; asm("add.rn.f32x2 %0, %1, %2;" : "=l"(d) : "l"(a), "l"(b)); return d;
}
__device__ __forceinline__ float rcpa(float x) {
    float r; asm("rcp.approx.f32 %0, %1;" : "=f"(r) : "f"(x)); return r;
}
__device__ __forceinline__ float ex2a(float x) {
    float r; asm("ex2.approx.f32 %0, %1;" : "=f"(r) : "f"(x)); return r;
}

__device__ __forceinline__ void cp16(unsigned saddr, const float* g) {
    asm volatile("cp.async.cg.shared.global [%0], [%1], 16;" :: "r"(saddr), "l"(g));
}

__device__ __forceinline__ float gelu1(float v) {
    return 0.5f * v * (1.0f + erff(v * 0.7071067811865476f));
}

// exact gelu on packed f32x2 via A&S 7.1.26 erf (abs err 1.5e-7)
__device__ __forceinline__ u64 gelu2(u64 v) {
    u64 s  = mul2(v, dup2(0.7071067811865476f));
    u64 x  = s & 0x7FFFFFFF7FFFFFFFULL;
    u64 dn = fma2(x, dup2(0.3275911f), dup2(1.0f));
    float d0, d1; upk2(dn, d0, d1);
    u64 t  = pk2(rcpa(d0), rcpa(d1));
    u64 p  = fma2(t, dup2(-1.061405429f), dup2(1.453152027f));
    p = fma2(p, t, dup2(-1.421413741f));
    p = fma2(p, t, dup2( 0.284496736f));
    p = fma2(p, t, dup2(-0.254829592f));
    p = mul2(p, t);
    u64 xx = mul2(x, x);
    u64 ea = mul2(xx, dup2(-1.4426950408889634f));
    float e0, e1; upk2(ea, e0, e1);
    u64 e  = pk2(ex2a(e0), ex2a(e1));
    u64 erfa = fma2(p, e, dup2(1.0f));
    u64 sgn  = s & 0x8000000080000000ULL;
    u64 erf  = erfa | sgn;
    u64 h    = fma2(erf, dup2(0.5f), dup2(0.5f));
    return mul2(v, h);
}

__device__ __forceinline__ float allredf(float v) {
    #pragma unroll
    for (int off = 16; off > 0; off >>= 1)
        v += __shfl_xor_sync(0xFFFFFFFFu, v, off);
    return v;
}

// ============================================================================
// Kernel 0: LayerNorm -> g_lnT[k][b]
// ============================================================================
__global__ __launch_bounds__(256)
void ln_kernel(const float* __restrict__ ada, const float* __restrict__ lg,
               const float* __restrict__ lb) {
    __shared__ float red[8];
    const int b = blockIdx.x, tid = threadIdx.x;
    const int lane = tid & 31, wrp = tid >> 5;

    float a[4];
    #pragma unroll
    for (int j = 0; j < 4; ++j) a[j] = ada[b * 1024 + tid + 256 * j];

    float s = a[0] + a[1] + a[2] + a[3];
    #pragma unroll
    for (int off = 16; off > 0; off >>= 1) s += __shfl_xor_sync(~0u, s, off);
    if (lane == 0) red[wrp] = s;
    __syncthreads();
    float mu = 0.f;
    #pragma unroll
    for (int w = 0; w < 8; ++w) mu += red[w];
    mu *= (1.0f / 1024.0f);
    __syncthreads();

    float ss = 0.f;
    #pragma unroll
    for (int j = 0; j < 4; ++j) { float d = a[j] - mu; ss += d * d; }
    #pragma unroll
    for (int off = 16; off > 0; off >>= 1) ss += __shfl_xor_sync(~0u, ss, off);
    if (lane == 0) red[wrp] = ss;
    __syncthreads();
    float var = 0.f;
    #pragma unroll
    for (int w = 0; w < 8; ++w) var += red[w];
    var *= (1.0f / 1024.0f);
    const float rs = rsqrtf(var + 1e-5f);

    #pragma unroll
    for (int j = 0; j < 4; ++j) {
        int k = tid + 256 * j;
        g_lnT[k * 16 + b] = (a[j] - mu) * rs * lg[k] + lb[k];
    }
}

// ============================================================================
// Kernel 1: h = gelu(LN @ W1 + b1) -> g_hT[k][b]
// 64 CTAs x 512 thr; CTA = 16 cols, 32-way k-split.
// ============================================================================
__global__ __launch_bounds__(512)
void h_kernel(const float* __restrict__ W1, const float* __restrict__ b1) {
    extern __shared__ float s[];
    const int tid = threadIdx.x;
    for (int i = tid; i < 4096; i += 512)
        ((float4*)s)[i] = ((const float4*)g_lnT)[i];
    __syncthreads();

    const int kg = tid >> 4, cl = tid & 15;   // kg 0..31
    const int col = (blockIdx.x << 4) + cl;

    u64 acc[8];
    #pragma unroll
    for (int j = 0; j < 8; ++j) acc[j] = 0ULL;

    const int k0 = kg * 32;
    #pragma unroll 4
    for (int k = k0; k < k0 + 32; ++k) {
        float w = __ldg(W1 + k * 1024 + col);
        u64 wd = dup2(w);
        const u64* hp = (const u64*)(s + k * 16);
        #pragma unroll
        for (int j = 0; j < 8; ++j) acc[j] = fma2(hp[j], wd, acc[j]);
    }
    __syncthreads();
    #pragma unroll
    for (int j = 0; j < 8; ++j) {
        float f0, f1; upk2(acc[j], f0, f1);
        s[tid * 17 + 2 * j]     = f0;
        s[tid * 17 + 2 * j + 1] = f1;
    }
    __syncthreads();

    if (tid < 256) {
        const int oc = tid & 15, ob = tid >> 4;   // ob = batch 0..15
        const int ocol = (blockIdx.x << 4) + oc;
        float v = b1[ocol];
        #pragma unroll
        for (int g = 0; g < 32; ++g) v += s[(g * 16 + oc) * 17 + ob];
        g_hT[ocol * 16 + ob] = gelu1(v);
    }
}

// ============================================================================
// Kernel 2: w = h @ W2 + b2 -> g_w (transposed [b][f][r][d])
// 256 CTAs x 256 thr; CTA = 128 cols (4/thread via float4), 8-way k-split.
// Double-buffered blocks of 4 k: prefetch next block while computing current.
// ============================================================================
#define WPAD 67
__global__ __launch_bounds__(256, 2)
void w_kernel(const float* __restrict__ W2, const float* __restrict__ b2) {
    extern __shared__ float s[];   // 16384 hT floats, then 8*32*67 reduction
    const int tid = threadIdx.x;
    for (int i = tid; i < 4096; i += 256)
        ((float4*)s)[i] = ((const float4*)g_hT)[i];
    __syncthreads();

    const int kg = tid >> 5, cl = tid & 31;
    const int col0 = (blockIdx.x << 7) + cl * 4;
    const int k0 = kg << 7;
    const float* bp = W2 + (size_t)k0 * 32768 + col0;

    u64 acc[4][8];
    #pragma unroll
    for (int c = 0; c < 4; ++c)
        #pragma unroll
        for (int j = 0; j < 8; ++j) acc[c][j] = 0ULL;

    float4 wb[2][4];
    #pragma unroll
    for (int j = 0; j < 4; ++j)
        wb[0][j] = __ldg((const float4*)(bp + (size_t)j * 32768));

    #pragma unroll 2
    for (int kb = 0; kb < 32; ++kb) {
        const int cur = kb & 1, nxt = cur ^ 1;
        if (kb < 31) {
            const float* np = bp + (size_t)(kb + 1) * 4 * 32768;
            #pragma unroll
            for (int j = 0; j < 4; ++j)
                wb[nxt][j] = __ldg((const float4*)(np + (size_t)j * 32768));
        }
        #pragma unroll
        for (int j = 0; j < 4; ++j) {
            const u64* hp = (const u64*)(s + (k0 + kb * 4 + j) * 16);
            float4 w = wb[cur][j];
            u64 w0 = dup2(w.x), w1 = dup2(w.y), w2 = dup2(w.z), w3 = dup2(w.w);
            #pragma unroll
            for (int jj = 0; jj < 8; ++jj) {
                u64 h2 = hp[jj];
                acc[0][jj] = fma2(h2, w0, acc[0][jj]);
                acc[1][jj] = fma2(h2, w1, acc[1][jj]);
                acc[2][jj] = fma2(h2, w2, acc[2][jj]);
                acc[3][jj] = fma2(h2, w3, acc[3][jj]);
            }
        }
    }
    __syncthreads();   // done reading hT
    #pragma unroll
    for (int c = 0; c < 4; ++c)
        #pragma unroll
        for (int j = 0; j < 8; ++j) {
            float f0, f1; upk2(acc[c][j], f0, f1);
            s[(kg * 32 + cl) * WPAD + c * 16 + 2 * j]     = f0;
            s[(kg * 32 + cl) * WPAD + c * 16 + 2 * j + 1] = f1;
        }
    __syncthreads();

    // 2048 outputs per CTA, 8 per thread; scatter into transposed layout
    const int ocl = tid & 31, og = tid >> 5;
    #pragma unroll
    for (int m = 0; m < 8; ++m) {
        const int f = og * 8 + m;           // f = c*16 + b
        const int c = f >> 4, b = f & 15;
        float v = 0.f;
        #pragma unroll
        for (int g = 0; g < 8; ++g) v += s[(g * 32 + ocl) * WPAD + f];
        const int col = (blockIdx.x << 7) + ocl * 4 + c;
        v += b2[col];
        const int q = col >> 13, idx = col & 8191;
        const int d = idx >> 3, r = idx & 7;
        g_w[b * WSTRIDE + q * 8192 + r * 1024 + d] = v;
    }
}

// ============================================================================
// Kernel 3: fused main path, d-packed f32x2 (zero-MOV inner loops).
// CTA = 256 thr (8 warps), 4 rows/warp, 32 rows/CTA. grid = 512.
// Accumulator pairs run over adjacent d columns; both fma2 operands come
// straight from LDS.128/LDG.128 register pairs. P2/P3 do 2-row passes so the
// loop-invariant dup2(t1)/dup2(t2) sets fit in 128 regs.
// smem: [a1 | bb1 | a2] = 96KB; bb2 overwrites a1 slot after P1.
// ============================================================================
__global__ __launch_bounds__(256, 2)
void main_kernel(const float* __restrict__ x, float* __restrict__ out) {
    extern __shared__ float smem[];
    float* sA1 = smem;            // a1, then bb2
    float* sB1 = smem + 8192;     // bb1
    float* sA2 = smem + 16384;    // a2

    const int tid  = threadIdx.x;
    const int lane = tid & 31, wrp = tid >> 5;
    const int b    = blockIdx.x >> 5;
    const int row0 = ((blockIdx.x & 31) << 5) + (wrp << 2);
    const float* gw = g_w + b * WSTRIDE;

    const unsigned sbase = (unsigned)__cvta_generic_to_shared(smem);

    // G1: a1
    for (int i = tid; i < 2048; i += 256)
        cp16(sbase + i * 16, gw + i * 4);
    asm volatile("cp.async.commit_group;");
    // G2: bb1 + a2 (contiguous in g_w)
    for (int i = tid; i < 4096; i += 256)
        cp16(sbase + 32768 + i * 16, gw + 8192 + i * 4);
    asm volatile("cp.async.commit_group;");

    asm volatile("cp.async.wait_group 1;");   // a1 ready
    __syncthreads();

    const float* xr = x + (b * 1024 + row0) * 1024;

    // ---- P1: t1p[row][r], pairs packed over (d, d+1) ----
    u64 t1p[4][8];
    #pragma unroll
    for (int row = 0; row < 4; ++row)
        #pragma unroll
        for (int r = 0; r < 8; ++r) t1p[row][r] = 0ULL;

    #pragma unroll 2
    for (int i = 0; i < 8; ++i) {
        const int d0 = (lane << 2) + (i << 7);
        float4 xv[4];
        #pragma unroll
        for (int rr = 0; rr < 4; ++rr) xv[rr] = __ldg((const float4*)(xr + rr * 1024 + d0));
        #pragma unroll
        for (int r = 0; r < 8; ++r) {
            float4 a = *(const float4*)(sA1 + (r << 10) + d0);
            u64 a0 = ((const u64*)&a)[0], a1q = ((const u64*)&a)[1];
            #pragma unroll
            for (int rr = 0; rr < 4; ++rr) {
                t1p[rr][r] = fma2(((const u64*)&xv[rr])[0], a0,  t1p[rr][r]);
                t1p[rr][r] = fma2(((const u64*)&xv[rr])[1], a1q, t1p[rr][r]);
            }
        }
    }
    // horizontal pair-sum first, then scalar warp reduce
    float t1s[4][8];
    #pragma unroll
    for (int row = 0; row < 4; ++row)
        #pragma unroll
        for (int r = 0; r < 8; ++r) {
            float lo, hi; upk2(t1p[row][r], lo, hi);
            t1s[row][r] = allredf(lo + hi);
        }

    __syncthreads();   // all warps done reading a1

    // G3: bb2 into a1 slot (overlaps with P2)
    for (int i = tid; i < 2048; i += 256)
        cp16(sbase + i * 16, gw + 24576 + i * 4);
    asm volatile("cp.async.commit_group;");

    asm volatile("cp.async.wait_group 1;");   // bb1 + a2 ready
    __syncthreads();

    // ---- P2: two passes of 2 rows ----
    u64 t2p[4][8];
    #pragma unroll
    for (int row = 0; row < 4; ++row)
        #pragma unroll
        for (int r = 0; r < 8; ++r) t2p[row][r] = 0ULL;

    #pragma unroll
    for (int pass = 0; pass < 2; ++pass) {
        const int r0 = pass << 1;
        u64 dupT[2][8];
        #pragma unroll
        for (int rr = 0; rr < 2; ++rr)
            #pragma unroll
            for (int r = 0; r < 8; ++r) dupT[rr][r] = dup2(t1s[r0 + rr][r]);

        #pragma unroll 2
        for (int i = 0; i < 16; ++i) {
            const int d0 = (lane << 1) + (i << 6);
            u64 z0 = 0ULL, z1 = 0ULL;
            #pragma unroll
            for (int r = 0; r < 8; ++r) {
                u64 bbq = *(const u64*)(sB1 + (r << 10) + d0);
                z0 = fma2(dupT[0][r], bbq, z0);
                z1 = fma2(dupT[1][r], bbq, z1);
            }
            z0 = gelu2(z0);
            z1 = gelu2(z1);
            #pragma unroll
            for (int r = 0; r < 8; ++r) {
                u64 a2q = *(const u64*)(sA2 + (r << 10) + d0);
                t2p[r0][r]     = fma2(z0, a2q, t2p[r0][r]);
                t2p[r0 + 1][r] = fma2(z1, a2q, t2p[r0 + 1][r]);
            }
        }
    }
    float t2s[4][8];
    #pragma unroll
    for (int row = 0; row < 4; ++row)
        #pragma unroll
        for (int r = 0; r < 8; ++r) {
            float lo, hi; upk2(t2p[row][r], lo, hi);
            t2s[row][r] = allredf(lo + hi);
        }

    asm volatile("cp.async.wait_group 0;");   // bb2 ready
    __syncthreads();

    // ---- P3: out = t2 . bb2 + x, two passes of 2 rows, 4-d blocks ----
    float* orow = out + (b * 1024 + row0) * 1024;
    #pragma unroll
    for (int pass = 0; pass < 2; ++pass) {
        const int r0 = pass << 1;
        u64 dupU[2][8];
        #pragma unroll
        for (int rr = 0; rr < 2; ++rr)
            #pragma unroll
            for (int r = 0; r < 8; ++r) dupU[rr][r] = dup2(t2s[r0 + rr][r]);

        #pragma unroll 2
        for (int i = 0; i < 8; ++i) {
            const int d0 = (lane << 2) + (i << 7);
            float4 xv[2];
            #pragma unroll
            for (int rr = 0; rr < 2; ++rr)
                xv[rr] = __ldg((const float4*)(xr + (r0 + rr) * 1024 + d0));
            u64 o[2][2];
            #pragma unroll
            for (int rr = 0; rr < 2; ++rr) {
                o[rr][0] = ((const u64*)&xv[rr])[0];
                o[rr][1] = ((const u64*)&xv[rr])[1];
            }
            #pragma unroll
            for (int r = 0; r < 8; ++r) {
                float4 bb = *(const float4*)(sA1 + (r << 10) + d0);
                u64 b0 = ((const u64*)&bb)[0], b1q = ((const u64*)&bb)[1];
                #pragma unroll
                for (int rr = 0; rr < 2; ++rr) {
                    o[rr][0] = fma2(dupU[rr][r], b0,  o[rr][0]);
                    o[rr][1] = fma2(dupU[rr][r], b1q, o[rr][1]);
                }
            }
            #pragma unroll
            for (int rr = 0; rr < 2; ++rr) {
                float4 ov;
                ((u64*)&ov)[0] = o[rr][0];
                ((u64*)&ov)[1] = o[rr][1];
                *(float4*)(orow + (r0 + rr) * 1024 + d0) = ov;
            }
        }
    }
}

// ============================================================================
// launch
// ============================================================================
extern "C" void kernel_launch(void* const* d_in, const int* in_sizes, int n_in,
                              void* d_out, int out_size) {
    const float* x    = (const float*)d_in[0];
    const float* ada  = (const float*)d_in[1];
    const float* ln_g = (const float*)d_in[2];
    const float* ln_b = (const float*)d_in[3];
    const float* W1   = (const float*)d_in[4];
    const float* b1   = (const float*)d_in[5];
    const float* W2   = (const float*)d_in[6];
    const float* b2   = (const float*)d_in[7];
    float* out = (float*)d_out;

    const int h_smem = 65536;
    const int w_smem = 8 * 32 * WPAD * 4;       // 68608
    const int m_smem = 3 * 8192 * 4;            // 98304 (96KB)

    cudaFuncSetAttribute(h_kernel,    cudaFuncAttributeMaxDynamicSharedMemorySize, h_smem);
    cudaFuncSetAttribute(w_kernel,    cudaFuncAttributeMaxDynamicSharedMemorySize, w_smem);
    cudaFuncSetAttribute(main_kernel, cudaFuncAttributeMaxDynamicSharedMemorySize, m_smem);

    ln_kernel<<<16, 256>>>(ada, ln_g, ln_b);
    h_kernel<<<64, 512, h_smem>>>(W1, b1);
    w_kernel<<<256, 256, w_smem>>>(W2, b2);
    main_kernel<<<512, 256, m_smem>>>(x, out);
}

// round 7
// speedup vs baseline: 1.1075x; 1.1075x over previous
#include <cuda_runtime.h>
#include <cstdint>

typedef unsigned long long u64;

// ---------------- problem constants ----------------
#define BATCH 16
#define WSTRIDE 32768   // per-batch factor block: 4 * 1024 * 8

// ---------------- device scratch ----------------
__device__ float g_lnT[1024 * 16];   // LN(ada) transposed: [k][b]
__device__ float g_hT [1024 * 16];   // h transposed: [k][b]
// factors, PRE-TRANSPOSED: [b][f][r][d], f: 0=a1, 1=bb1, 2=a2, 3=bb2
__device__ float g_w  [16 * 32768];

// ---------------- f32x2 helpers ----------------
__device__ __forceinline__ u64 pk2(float lo, float hi) {
    u64 r; asm("mov.b64 %0, {%1,%2};" : "=l"(r) : "f"(lo), "f"(hi)); return r;
}
__device__ __forceinline__ void upk2(u64 v, float& lo, float& hi) {
    asm("mov.b64 {%0,%1}, %2;" : "=f"(lo), "=f"(hi) : "l"(v));
}
__device__ __forceinline__ u64 dup2(float x) { return pk2(x, x); }
__device__ __forceinline__ u64 fma2(u64 a, u64 b, u64 c) {
    u64 d; asm("fma.rn.f32x2 %0, %1, %2, %3;" : "=l"(d) : "l"(a), "l"(b), "l"(c)); return d;
}
__device__ __forceinline__ u64 mul2(u64 a, u64 b) {
    u64 d; asm("mul.rn.f32x2 %0, %1, %2;" : "=l"(d) : "l"(a), "l"(b)); return d;
}
__device__ __forceinline__ u64 add2(u64 a, u64 b) {
    u64 d; asm("add.rn.f32x2 %0, %1, %2;" : "=l"(d) : "l"(a), "l"(b)); return d;
}
__device__ __forceinline__ float rcpa(float x) {
    float r; asm("rcp.approx.f32 %0, %1;" : "=f"(r) : "f"(x)); return r;
}
__device__ __forceinline__ float ex2a(float x) {
    float r; asm("ex2.approx.f32 %0, %1;" : "=f"(r) : "f"(x)); return r;
}

__device__ __forceinline__ void cp16(unsigned saddr, const float* g) {
    asm volatile("cp.async.cg.shared.global [%0], [%1], 16;" :: "r"(saddr), "l"(g));
}

__device__ __forceinline__ float gelu1(float v) {
    return 0.5f * v * (1.0f + erff(v * 0.7071067811865476f));
}

// tanh-form gelu on packed f32x2 (max abs err ~3e-4 vs exact; LoRA delta is
// ~1% of the output, so final rel_err contribution ~1e-5).
// gelu(v) = v * (1 - q), q = 1/(1 + e^{2y}), y = 0.79788456 v (1 + 0.044715 v^2)
__device__ __forceinline__ u64 gelu2t(u64 v) {
    u64 v2    = mul2(v, v);
    u64 inner = fma2(v2, dup2(0.0356774081f), dup2(0.7978845608f));
    u64 y     = mul2(v, inner);
    u64 u     = mul2(y, dup2(2.8853900818f));   // 2*log2(e)*y
    float u0, u1; upk2(u, u0, u1);
    float e0 = ex2a(u0), e1 = ex2a(u1);
    float q0 = rcpa(e0 + 1.0f), q1 = rcpa(e1 + 1.0f);
    u64 q = pk2(q0, q1);
    u64 h = fma2(q, dup2(-1.0f), dup2(1.0f));   // 1 - q
    return mul2(v, h);
}

__device__ __forceinline__ float allredf(float v) {
    #pragma unroll
    for (int off = 16; off > 0; off >>= 1)
        v += __shfl_xor_sync(0xFFFFFFFFu, v, off);
    return v;
}
__device__ __forceinline__ void allred2(u64& v) {
    #pragma unroll
    for (int off = 16; off > 0; off >>= 1) {
        u64 o = __shfl_xor_sync(0xFFFFFFFFu, v, off);
        v = add2(v, o);
    }
}

// ============================================================================
// Kernel 0: LayerNorm -> g_lnT[k][b]
// ============================================================================
__global__ __launch_bounds__(256)
void ln_kernel(const float* __restrict__ ada, const float* __restrict__ lg,
               const float* __restrict__ lb) {
    __shared__ float red[8];
    const int b = blockIdx.x, tid = threadIdx.x;
    const int lane = tid & 31, wrp = tid >> 5;

    float a[4];
    #pragma unroll
    for (int j = 0; j < 4; ++j) a[j] = ada[b * 1024 + tid + 256 * j];

    float s = a[0] + a[1] + a[2] + a[3];
    #pragma unroll
    for (int off = 16; off > 0; off >>= 1) s += __shfl_xor_sync(~0u, s, off);
    if (lane == 0) red[wrp] = s;
    __syncthreads();
    float mu = 0.f;
    #pragma unroll
    for (int w = 0; w < 8; ++w) mu += red[w];
    mu *= (1.0f / 1024.0f);
    __syncthreads();

    float ss = 0.f;
    #pragma unroll
    for (int j = 0; j < 4; ++j) { float d = a[j] - mu; ss += d * d; }
    #pragma unroll
    for (int off = 16; off > 0; off >>= 1) ss += __shfl_xor_sync(~0u, ss, off);
    if (lane == 0) red[wrp] = ss;
    __syncthreads();
    float var = 0.f;
    #pragma unroll
    for (int w = 0; w < 8; ++w) var += red[w];
    var *= (1.0f / 1024.0f);
    const float rs = rsqrtf(var + 1e-5f);

    #pragma unroll
    for (int j = 0; j < 4; ++j) {
        int k = tid + 256 * j;
        g_lnT[k * 16 + b] = (a[j] - mu) * rs * lg[k] + lb[k];
    }
}

// ============================================================================
// Kernel 1: h = gelu(LN @ W1 + b1) -> g_hT[k][b]
// 64 CTAs x 512 thr; CTA = 16 cols, 32-way k-split.
// ============================================================================
__global__ __launch_bounds__(512)
void h_kernel(const float* __restrict__ W1, const float* __restrict__ b1) {
    extern __shared__ float s[];
    const int tid = threadIdx.x;
    for (int i = tid; i < 4096; i += 512)
        ((float4*)s)[i] = ((const float4*)g_lnT)[i];
    __syncthreads();

    const int kg = tid >> 4, cl = tid & 15;   // kg 0..31
    const int col = (blockIdx.x << 4) + cl;

    u64 acc[8];
    #pragma unroll
    for (int j = 0; j < 8; ++j) acc[j] = 0ULL;

    const int k0 = kg * 32;
    #pragma unroll 4
    for (int k = k0; k < k0 + 32; ++k) {
        float w = __ldg(W1 + k * 1024 + col);
        u64 wd = dup2(w);
        const u64* hp = (const u64*)(s + k * 16);
        #pragma unroll
        for (int j = 0; j < 8; ++j) acc[j] = fma2(hp[j], wd, acc[j]);
    }
    __syncthreads();
    #pragma unroll
    for (int j = 0; j < 8; ++j) {
        float f0, f1; upk2(acc[j], f0, f1);
        s[tid * 17 + 2 * j]     = f0;
        s[tid * 17 + 2 * j + 1] = f1;
    }
    __syncthreads();

    if (tid < 256) {
        const int oc = tid & 15, ob = tid >> 4;   // ob = batch 0..15
        const int ocol = (blockIdx.x << 4) + oc;
        float v = b1[ocol];
        #pragma unroll
        for (int g = 0; g < 32; ++g) v += s[(g * 16 + oc) * 17 + ob];
        g_hT[ocol * 16 + ob] = gelu1(v);
    }
}

// ============================================================================
// Kernel 2: w = h @ W2 + b2 -> g_w (transposed [b][f][r][d])   [R5 version]
// 256 CTAs x 256 thr; CTA = 128 cols (4/thread via float4), 8-way k-split.
// ============================================================================
#define WPAD 67
__global__ __launch_bounds__(256, 2)
void w_kernel(const float* __restrict__ W2, const float* __restrict__ b2) {
    extern __shared__ float s[];   // 16384 hT floats, then 8*32*67 reduction
    const int tid = threadIdx.x;
    for (int i = tid; i < 4096; i += 256)
        ((float4*)s)[i] = ((const float4*)g_hT)[i];
    __syncthreads();

    const int kg = tid >> 5, cl = tid & 31;
    const int col0 = (blockIdx.x << 7) + cl * 4;

    u64 acc[4][8];
    #pragma unroll
    for (int c = 0; c < 4; ++c)
        #pragma unroll
        for (int j = 0; j < 8; ++j) acc[c][j] = 0ULL;

    const int k0 = kg << 7;
    #pragma unroll 8
    for (int k = k0; k < k0 + 128; ++k) {
        float4 w = __ldg((const float4*)(W2 + (size_t)k * 32768 + col0));
        const u64* hp = (const u64*)(s + k * 16);
        u64 w0 = dup2(w.x), w1 = dup2(w.y), w2 = dup2(w.z), w3 = dup2(w.w);
        #pragma unroll
        for (int j = 0; j < 8; ++j) {
            u64 h2 = hp[j];
            acc[0][j] = fma2(h2, w0, acc[0][j]);
            acc[1][j] = fma2(h2, w1, acc[1][j]);
            acc[2][j] = fma2(h2, w2, acc[2][j]);
            acc[3][j] = fma2(h2, w3, acc[3][j]);
        }
    }
    __syncthreads();   // done reading hT
    #pragma unroll
    for (int c = 0; c < 4; ++c)
        #pragma unroll
        for (int j = 0; j < 8; ++j) {
            float f0, f1; upk2(acc[c][j], f0, f1);
            s[(kg * 32 + cl) * WPAD + c * 16 + 2 * j]     = f0;
            s[(kg * 32 + cl) * WPAD + c * 16 + 2 * j + 1] = f1;
        }
    __syncthreads();

    const int ocl = tid & 31, og = tid >> 5;
    #pragma unroll
    for (int m = 0; m < 8; ++m) {
        const int f = og * 8 + m;           // f = c*16 + b
        const int c = f >> 4, b = f & 15;
        float v = 0.f;
        #pragma unroll
        for (int g = 0; g < 8; ++g) v += s[(g * 32 + ocl) * WPAD + f];
        const int col = (blockIdx.x << 7) + ocl * 4 + c;
        v += b2[col];
        const int q = col >> 13, idx = col & 8191;
        const int d = idx >> 3, r = idx & 7;
        g_w[b * WSTRIDE + q * 8192 + r * 1024 + d] = v;
    }
}

// ============================================================================
// Kernel 3: fused main path (hybrid).
//   P1: d-packed, mov-free (R6 style)
//   P2: row-packed single d-sweep (R5 style) + cheap tanh gelu
//   P3: d-packed SINGLE pass with loop-invariant dup2(t2)
// CTA = 256 thr (8 warps), 4 rows/warp, 32 rows/CTA. grid = 512.
// smem: [a1 | bb1 | a2] = 96KB; bb2 overwrites a1 slot after P1.
// ============================================================================
__global__ __launch_bounds__(256, 2)
void main_kernel(const float* __restrict__ x, float* __restrict__ out) {
    extern __shared__ float smem[];
    float* sA1 = smem;            // a1, then bb2
    float* sB1 = smem + 8192;     // bb1
    float* sA2 = smem + 16384;    // a2

    const int tid  = threadIdx.x;
    const int lane = tid & 31, wrp = tid >> 5;
    const int b    = blockIdx.x >> 5;
    const int row0 = ((blockIdx.x & 31) << 5) + (wrp << 2);
    const float* gw = g_w + b * WSTRIDE;

    const unsigned sbase = (unsigned)__cvta_generic_to_shared(smem);

    // G1: a1
    for (int i = tid; i < 2048; i += 256)
        cp16(sbase + i * 16, gw + i * 4);
    asm volatile("cp.async.commit_group;");
    // G2: bb1 + a2 (contiguous in g_w)
    for (int i = tid; i < 4096; i += 256)
        cp16(sbase + 32768 + i * 16, gw + 8192 + i * 4);
    asm volatile("cp.async.commit_group;");

    asm volatile("cp.async.wait_group 1;");   // a1 ready
    __syncthreads();

    const float* xr = x + (b * 1024 + row0) * 1024;

    // ---- P1: t1p[row][r], pairs packed over (d, d+1); zero movs ----
    u64 t1p[4][8];
    #pragma unroll
    for (int row = 0; row < 4; ++row)
        #pragma unroll
        for (int r = 0; r < 8; ++r) t1p[row][r] = 0ULL;

    #pragma unroll 2
    for (int i = 0; i < 8; ++i) {
        const int d0 = (lane << 2) + (i << 7);
        float4 xv[4];
        #pragma unroll
        for (int rr = 0; rr < 4; ++rr) xv[rr] = __ldg((const float4*)(xr + rr * 1024 + d0));
        #pragma unroll
        for (int r = 0; r < 8; ++r) {
            float4 a = *(const float4*)(sA1 + (r << 10) + d0);
            u64 a0 = ((const u64*)&a)[0], a1q = ((const u64*)&a)[1];
            #pragma unroll
            for (int rr = 0; rr < 4; ++rr) {
                t1p[rr][r] = fma2(((const u64*)&xv[rr])[0], a0,  t1p[rr][r]);
                t1p[rr][r] = fma2(((const u64*)&xv[rr])[1], a1q, t1p[rr][r]);
            }
        }
    }
    // pair-sum + scalar warp-reduce
    float t1s[4][8];
    #pragma unroll
    for (int row = 0; row < 4; ++row)
        #pragma unroll
        for (int r = 0; r < 8; ++r) {
            float lo, hi; upk2(t1p[row][r], lo, hi);
            t1s[row][r] = allredf(lo + hi);
        }
    // repack over rows for P2: (row0,row1), (row2,row3)
    u64 t1row[2][8];
    #pragma unroll
    for (int r = 0; r < 8; ++r) {
        t1row[0][r] = pk2(t1s[0][r], t1s[1][r]);
        t1row[1][r] = pk2(t1s[2][r], t1s[3][r]);
    }

    __syncthreads();   // all warps done reading a1

    // G3: bb2 into a1 slot (overlaps with P2)
    for (int i = tid; i < 2048; i += 256)
        cp16(sbase + i * 16, gw + 24576 + i * 4);
    asm volatile("cp.async.commit_group;");

    asm volatile("cp.async.wait_group 1;");   // bb1 + a2 ready
    __syncthreads();

    // ---- P2: row-packed, single d-sweep, 2 cols/lane/iter ----
    u64 t2p[2][8];
    #pragma unroll
    for (int j = 0; j < 2; ++j)
        #pragma unroll
        for (int r = 0; r < 8; ++r) t2p[j][r] = 0ULL;

    #pragma unroll 2
    for (int i = 0; i < 16; ++i) {
        const int d0 = (lane << 1) + (i << 6);
        float2 bv[8];
        #pragma unroll
        for (int r = 0; r < 8; ++r) bv[r] = *(const float2*)(sB1 + (r << 10) + d0);
        u64 z00 = 0ULL, z10 = 0ULL, z01 = 0ULL, z11 = 0ULL;
        #pragma unroll
        for (int r = 0; r < 8; ++r) {
            u64 b0 = dup2(bv[r].x), b1d = dup2(bv[r].y);
            z00 = fma2(t1row[0][r], b0,  z00);
            z10 = fma2(t1row[1][r], b0,  z10);
            z01 = fma2(t1row[0][r], b1d, z01);
            z11 = fma2(t1row[1][r], b1d, z11);
        }
        z00 = gelu2t(z00); z10 = gelu2t(z10);
        z01 = gelu2t(z01); z11 = gelu2t(z11);
        float2 av[8];
        #pragma unroll
        for (int r = 0; r < 8; ++r) av[r] = *(const float2*)(sA2 + (r << 10) + d0);
        #pragma unroll
        for (int r = 0; r < 8; ++r) {
            u64 a0 = dup2(av[r].x), a1d = dup2(av[r].y);
            t2p[0][r] = fma2(z00, a0,  t2p[0][r]);
            t2p[1][r] = fma2(z10, a0,  t2p[1][r]);
            t2p[0][r] = fma2(z01, a1d, t2p[0][r]);
            t2p[1][r] = fma2(z11, a1d, t2p[1][r]);
        }
    }
    // vector warp-reduce (pairs stay row-packed), then build dup'd t2 per row
    #pragma unroll
    for (int j = 0; j < 2; ++j)
        #pragma unroll
        for (int r = 0; r < 8; ++r) allred2(t2p[j][r]);

    u64 dupU[4][8];
    #pragma unroll
    for (int r = 0; r < 8; ++r) {
        float a, bq, c, d;
        upk2(t2p[0][r], a, bq);
        upk2(t2p[1][r], c, d);
        dupU[0][r] = dup2(a);
        dupU[1][r] = dup2(bq);
        dupU[2][r] = dup2(c);
        dupU[3][r] = dup2(d);
    }

    asm volatile("cp.async.wait_group 0;");   // bb2 ready
    __syncthreads();

    // ---- P3: single pass, d-packed, mov-free inner loop ----
    float* orow = out + (b * 1024 + row0) * 1024;
    #pragma unroll 2
    for (int i = 0; i < 8; ++i) {
        const int d0 = (lane << 2) + (i << 7);
        float4 xv[4];
        #pragma unroll
        for (int rr = 0; rr < 4; ++rr)
            xv[rr] = __ldg((const float4*)(xr + rr * 1024 + d0));
        u64 o[4][2];
        #pragma unroll
        for (int rr = 0; rr < 4; ++rr) {
            o[rr][0] = ((const u64*)&xv[rr])[0];
            o[rr][1] = ((const u64*)&xv[rr])[1];
        }
        #pragma unroll
        for (int r = 0; r < 8; ++r) {
            float4 bb = *(const float4*)(sA1 + (r << 10) + d0);
            u64 b0 = ((const u64*)&bb)[0], b1q = ((const u64*)&bb)[1];
            #pragma unroll
            for (int rr = 0; rr < 4; ++rr) {
                o[rr][0] = fma2(dupU[rr][r], b0,  o[rr][0]);
                o[rr][1] = fma2(dupU[rr][r], b1q, o[rr][1]);
            }
        }
        #pragma unroll
        for (int rr = 0; rr < 4; ++rr) {
            float4 ov;
            ((u64*)&ov)[0] = o[rr][0];
            ((u64*)&ov)[1] = o[rr][1];
            *(float4*)(orow + rr * 1024 + d0) = ov;
        }
    }
}

// ============================================================================
// launch
// ============================================================================
extern "C" void kernel_launch(void* const* d_in, const int* in_sizes, int n_in,
                              void* d_out, int out_size) {
    const float* x    = (const float*)d_in[0];
    const float* ada  = (const float*)d_in[1];
    const float* ln_g = (const float*)d_in[2];
    const float* ln_b = (const float*)d_in[3];
    const float* W1   = (const float*)d_in[4];
    const float* b1   = (const float*)d_in[5];
    const float* W2   = (const float*)d_in[6];
    const float* b2   = (const float*)d_in[7];
    float* out = (float*)d_out;

    const int h_smem = 65536;
    const int w_smem = 8 * 32 * WPAD * 4;       // 68608
    const int m_smem = 3 * 8192 * 4;            // 98304 (96KB)

    cudaFuncSetAttribute(h_kernel,    cudaFuncAttributeMaxDynamicSharedMemorySize, h_smem);
    cudaFuncSetAttribute(w_kernel,    cudaFuncAttributeMaxDynamicSharedMemorySize, w_smem);
    cudaFuncSetAttribute(main_kernel, cudaFuncAttributeMaxDynamicSharedMemorySize, m_smem);

    ln_kernel<<<16, 256>>>(ada, ln_g, ln_b);
    h_kernel<<<64, 512, h_smem>>>(W1, b1);
    w_kernel<<<256, 256, w_smem>>>(W2, b2);
    main_kernel<<<512, 256, m_smem>>>(x, out);
}